// round 1
// baseline (speedup 1.0000x reference)
#include <cuda_runtime.h>

// Problem constants (fixed shapes per setup_inputs)
#define B_    128
#define Q_    30
#define D_    200
#define E_    300
#define C_    128
#define V_    50000
#define QROWS 3840          // B_*Q_
#define DROWS 25600         // B_*D_
#define NROWS 29440         // QROWS + DROWS  (= 230 * 128)
#define NCOLS 768           // 128ch * (1 + 2 + 3) (type,tap) combos

// ---------------- device scratch (no runtime allocation allowed) ----------------
__device__ float g_W[E_ * NCOLS];                    // 0.9 MB  repacked conv weights
__device__ float g_P[(size_t)NROWS * NCOLS];         // 90 MB   per-(row,type,tap) partials
__device__ float g_qn[3 * (size_t)QROWS * C_];       // 5.9 MB  normalized q n-gram feats
__device__ float g_dn[3 * (size_t)DROWS * C_];       // 39 MB   normalized d n-gram feats
__device__ float g_feats[B_ * 99];                   // pooled features [B, 9*11]

// ---------------- K0: repack conv weights into W[300][768] ----------------
// col layout: [0,128)=w1 tap0 ; [128,256)=w2 tap0 ; [256,384)=w2 tap1 ;
//             [384,512)=w3 tap0 ; [512,640)=w3 tap1 ; [640,768)=w3 tap2
__global__ void kw_build(const float* __restrict__ w1,
                         const float* __restrict__ w2,
                         const float* __restrict__ w3)
{
    int idx = blockIdx.x * 256 + threadIdx.x;
    if (idx >= E_ * NCOLS) return;
    int e = idx / NCOLS, col = idx % NCOLS;
    float v;
    if (col < 128) {
        v = w1[col * E_ + e];                                   // [C,E,1]
    } else if (col < 384) {
        int u = col - 128; int t = u >> 7; int c = u & 127;
        v = w2[c * (E_ * 2) + e * 2 + t];                       // [C,E,2]
    } else {
        int u = col - 384; int t = u >> 7; int c = u & 127;
        v = w3[c * (E_ * 3) + e * 3 + t];                       // [C,E,3]
    }
    g_W[idx] = v;
}

// ---------------- K1: gather-GEMM P = Emb[tok] @ W ----------------
// M=29440 (rows: queries then docs), K=300, N=768. Block tile 128x64, thread tile 8x4.
__global__ __launch_bounds__(256) void k1_gemm(const float* __restrict__ emb,
                                               const int* __restrict__ qtok,
                                               const int* __restrict__ dtok)
{
    __shared__ float As[8][128];
    __shared__ float Bs[8][64];
    const int tid = threadIdx.x;
    const int bm0 = blockIdx.x * 128;
    const int bn0 = blockIdx.y * 64;
    const int tm = tid & 15, tn = tid >> 4;
    const int m0 = tm * 8, n0 = tn * 4;

    float acc[8][4];
#pragma unroll
    for (int i = 0; i < 8; i++)
#pragma unroll
        for (int j = 0; j < 4; j++) acc[i][j] = 0.f;

    // A-load role: each pair of threads loads one row's 8-wide k-slab (2x float4)
    const int am = tid >> 1;
    const int ah = (tid & 1) * 4;
    const int r  = bm0 + am;
    const int tok = (r < QROWS) ? qtok[r] : dtok[r - QROWS];
    const float* arow = emb + (size_t)tok * E_;

    // B-load role (tid<128): 8 rows x 16 float4
    const int bk = tid >> 4;
    const int bc = (tid & 15) * 4;

    for (int kc = 0; kc < E_; kc += 8) {
        int ka = kc + ah;
        float4 av = make_float4(0.f, 0.f, 0.f, 0.f);
        if (ka < E_) av = *(const float4*)(arow + ka);   // tok*1200B and ka*4 are 16B aligned
        As[ah + 0][am] = av.x; As[ah + 1][am] = av.y;
        As[ah + 2][am] = av.z; As[ah + 3][am] = av.w;
        if (tid < 128) {
            int kb = kc + bk;
            float4 bv = make_float4(0.f, 0.f, 0.f, 0.f);
            if (kb < E_) bv = *(const float4*)(g_W + kb * NCOLS + bn0 + bc);
            *(float4*)&Bs[bk][bc] = bv;
        }
        __syncthreads();
#pragma unroll
        for (int kk = 0; kk < 8; kk++) {
            float4 a0 = *(float4*)&As[kk][m0];
            float4 a1 = *(float4*)&As[kk][m0 + 4];
            float4 bv = *(float4*)&Bs[kk][n0];
            float a[8] = {a0.x, a0.y, a0.z, a0.w, a1.x, a1.y, a1.z, a1.w};
            float bb[4] = {bv.x, bv.y, bv.z, bv.w};
#pragma unroll
            for (int i = 0; i < 8; i++)
#pragma unroll
                for (int j = 0; j < 4; j++)
                    acc[i][j] += a[i] * bb[j];
        }
        __syncthreads();
    }
#pragma unroll
    for (int i = 0; i < 8; i++) {
        float4 st = make_float4(acc[i][0], acc[i][1], acc[i][2], acc[i][3]);
        *(float4*)&g_P[(size_t)(bm0 + m0 + i) * NCOLS + bn0 + n0] = st;
    }
}

// ---------------- K2: tap-combine + bias + ReLU + L2-normalize ----------------
// y_k[l,c] = relu(b_k[c] + sum_t P[l+t][col(k,t,c)])  (zero beyond sequence end)
__global__ void k2_combine(const float* __restrict__ cb1,
                           const float* __restrict__ cb2,
                           const float* __restrict__ cb3)
{
    const int r = blockIdx.x;
    const int c = threadIdx.x;
    int l, L, rr;
    const bool isq = (r < QROWS);
    if (isq) { rr = r;          l = r % Q_;  L = Q_; }
    else     { rr = r - QROWS;  l = rr % D_; L = D_; }

    const float* Pr = g_P + (size_t)r * NCOLS;
    float v1 = cb1[c] + Pr[c];
    float v2 = cb2[c] + Pr[128 + c];
    float v3 = cb3[c] + Pr[384 + c];
    if (l + 1 < L) { v2 += Pr[NCOLS + 256 + c]; v3 += Pr[NCOLS + 512 + c]; }
    if (l + 2 < L) { v3 += Pr[2 * NCOLS + 640 + c]; }
    v1 = fmaxf(v1, 0.f); v2 = fmaxf(v2, 0.f); v3 = fmaxf(v3, 0.f);

    float s1 = v1 * v1, s2 = v2 * v2, s3 = v3 * v3;
#pragma unroll
    for (int o = 16; o; o >>= 1) {
        s1 += __shfl_xor_sync(0xffffffffu, s1, o);
        s2 += __shfl_xor_sync(0xffffffffu, s2, o);
        s3 += __shfl_xor_sync(0xffffffffu, s3, o);
    }
    __shared__ float sred[3][4];
    const int lane = c & 31, w = c >> 5;
    if (lane == 0) { sred[0][w] = s1; sred[1][w] = s2; sred[2][w] = s3; }
    __syncthreads();
    float ss1 = sred[0][0] + sred[0][1] + sred[0][2] + sred[0][3];
    float ss2 = sred[1][0] + sred[1][1] + sred[1][2] + sred[1][3];
    float ss3 = sred[2][0] + sred[2][1] + sred[2][2] + sred[2][3];
    float n1 = v1 * (1.0f / (sqrtf(ss1) + 1e-13f));
    float n2 = v2 * (1.0f / (sqrtf(ss2) + 1e-13f));
    float n3 = v3 * (1.0f / (sqrtf(ss3) + 1e-13f));

    if (isq) {
        g_qn[((size_t)0 * QROWS + rr) * C_ + c] = n1;
        g_qn[((size_t)1 * QROWS + rr) * C_ + c] = n2;
        g_qn[((size_t)2 * QROWS + rr) * C_ + c] = n3;
    } else {
        g_dn[((size_t)0 * DROWS + rr) * C_ + c] = n1;
        g_dn[((size_t)1 * DROWS + rr) * C_ + c] = n2;
        g_dn[((size_t)2 * DROWS + rr) * C_ + c] = n3;
    }
}

// ---------------- K3: fused cosine GEMM + RBF soft-binning + log pooling ----------------
// One block per (batch b, pair). cos[30x200] via smem GEMM, RBF K=11 per element,
// per-(q,kernel) sums reduced via smem atomics, then masked log pooling.
__global__ __launch_bounds__(128) void k3_pool(const int* __restrict__ qtok,
                                               const int* __restrict__ dtok)
{
    const float MU[11]  = {1.0f, 0.9f, 0.7f, 0.5f, 0.3f, 0.1f,
                           -0.1f, -0.3f, -0.5f, -0.7f, -0.9f};
    const float IS2[11] = {500000.0f, 50.f, 50.f, 50.f, 50.f, 50.f,
                           50.f, 50.f, 50.f, 50.f, 50.f};   // 1/(2*sigma^2)

    __shared__ float qsT[128][36];   // [c][q], q padded to 32
    __shared__ float dsT[128][36];   // [c][d-chunk of 32]
    __shared__ float spk[32][11];
    __shared__ float qm[32];
    __shared__ float dm[224];

    const int b = blockIdx.x, pair = blockIdx.y;
    const int qi = pair / 3, dj = pair % 3;
    const int tid = threadIdx.x;

    if (tid < 32) qm[tid] = (tid < Q_ && qtok[b * Q_ + tid] > 0) ? 1.f : 0.f;
    for (int i = tid; i < 224; i += 128)
        dm[i] = (i < D_ && dtok[b * D_ + i] > 0) ? 1.f : 0.f;
    for (int i = tid; i < 32 * 11; i += 128) (&spk[0][0])[i] = 0.f;

    const float* qbase = g_qn + ((size_t)qi * QROWS + b * Q_) * C_;
    for (int i = 0; i < Q_; i++)
        qsT[tid][i] = qbase[(size_t)i * C_ + tid];
    qsT[tid][30] = 0.f; qsT[tid][31] = 0.f;

    const float* dbase = g_dn + ((size_t)dj * DROWS + b * D_) * C_;

    const int ty = tid >> 3, tx = tid & 7;
    const int q0 = ty * 2, d0 = tx * 4;

    float pk[2][11];
#pragma unroll
    for (int i = 0; i < 2; i++)
#pragma unroll
        for (int kk = 0; kk < 11; kk++) pk[i][kk] = 0.f;

    __syncthreads();

    for (int ch = 0; ch < 7; ch++) {
        const int dst = ch * 32;
#pragma unroll 4
        for (int i = 0; i < 32; i++) {
            int d = dst + i;
            dsT[tid][i] = (d < D_) ? dbase[(size_t)d * C_ + tid] : 0.f;
        }
        __syncthreads();

        float cs[2][4];
#pragma unroll
        for (int i = 0; i < 2; i++)
#pragma unroll
            for (int j = 0; j < 4; j++) cs[i][j] = 0.f;

#pragma unroll 8
        for (int k = 0; k < 128; k++) {
            float2 a  = *(float2*)&qsT[k][q0];
            float4 bv = *(float4*)&dsT[k][d0];
            cs[0][0] += a.x * bv.x; cs[0][1] += a.x * bv.y;
            cs[0][2] += a.x * bv.z; cs[0][3] += a.x * bv.w;
            cs[1][0] += a.y * bv.x; cs[1][1] += a.y * bv.y;
            cs[1][2] += a.y * bv.z; cs[1][3] += a.y * bv.w;
        }

#pragma unroll
        for (int i = 0; i < 2; i++) {
            float qmi = qm[q0 + i];
#pragma unroll
            for (int j = 0; j < 4; j++) {
                float m  = qmi * dm[dst + d0 + j];
                float cm = cs[i][j] * m;          // cos masked, matches reference
#pragma unroll
                for (int kk = 0; kk < 11; kk++) {
                    float df = cm - MU[kk];
                    pk[i][kk] += m * __expf(-df * df * IS2[kk]);
                }
            }
        }
        __syncthreads();
    }

#pragma unroll
    for (int i = 0; i < 2; i++)
#pragma unroll
        for (int kk = 0; kk < 11; kk++)
            atomicAdd(&spk[q0 + i][kk], pk[i][kk]);
    __syncthreads();

    if (tid < 11) {
        float f = 0.f;
        for (int q = 0; q < Q_; q++)
            f += logf(fmaxf(spk[q][tid], 1e-10f)) * 0.01f * qm[q];
        g_feats[(b * 9 + pair) * 11 + tid] = f;
    }
}

// ---------------- K4: final dense [B,99] @ w[99] ----------------
__global__ void k4_out(const float* __restrict__ dw, float* __restrict__ out)
{
    int b = threadIdx.x;
    float f = 0.f;
#pragma unroll
    for (int j = 0; j < 99; j++) f += g_feats[b * 99 + j] * dw[j];
    out[b] = f;
}

// ---------------- launch ----------------
extern "C" void kernel_launch(void* const* d_in, const int* in_sizes, int n_in,
                              void* d_out, int out_size)
{
    (void)in_sizes; (void)n_in; (void)out_size;
    const int*   qtok = (const int*)d_in[0];
    const int*   dtok = (const int*)d_in[1];
    const float* emb  = (const float*)d_in[2];
    const float* w1   = (const float*)d_in[3];
    const float* w2   = (const float*)d_in[4];
    const float* w3   = (const float*)d_in[5];
    const float* cb1  = (const float*)d_in[6];
    const float* cb2  = (const float*)d_in[7];
    const float* cb3  = (const float*)d_in[8];
    const float* dw   = (const float*)d_in[9];
    float* out = (float*)d_out;

    kw_build<<<(E_ * NCOLS + 255) / 256, 256>>>(w1, w2, w3);
    k1_gemm<<<dim3(230, 12), 256>>>(emb, qtok, dtok);
    k2_combine<<<NROWS, 128>>>(cb1, cb2, cb3);
    k3_pool<<<dim3(128, 9), 128>>>(qtok, dtok);
    k4_out<<<1, 128>>>(dw, out);
}

// round 2
// speedup vs baseline: 1.4810x; 1.4810x over previous
#include <cuda_runtime.h>

// Problem constants (fixed shapes per setup_inputs)
#define B_    128
#define Q_    30
#define D_    200
#define E_    300
#define C_    128
#define QROWS 3840          // B_*Q_
#define DROWS 25600         // B_*D_
#define NROWS 29440         // QROWS + DROWS  (= 230 * 128)
#define NCOLS 768           // 128ch * (1 + 2 + 3) (type,tap) combos

typedef unsigned long long u64;

// ---------------- packed f32x2 helpers (Blackwell sm_103a) ----------------
__device__ __forceinline__ u64 dupf(float x) {
    u64 r; unsigned xi = __float_as_uint(x);
    asm("mov.b64 %0, {%1, %1};" : "=l"(r) : "r"(xi));
    return r;
}
__device__ __forceinline__ u64 packf(float lo, float hi) {
    u64 r; unsigned a = __float_as_uint(lo), b = __float_as_uint(hi);
    asm("mov.b64 %0, {%1, %2};" : "=l"(r) : "r"(a), "r"(b));
    return r;
}
__device__ __forceinline__ void unpackf(u64 v, float& lo, float& hi) {
    unsigned a, b;
    asm("mov.b64 {%0, %1}, %2;" : "=r"(a), "=r"(b) : "l"(v));
    lo = __uint_as_float(a); hi = __uint_as_float(b);
}
__device__ __forceinline__ void ffma2(u64& d, u64 a, u64 b) {
    asm("fma.rn.f32x2 %0, %1, %2, %0;" : "+l"(d) : "l"(a), "l"(b));
}
__device__ __forceinline__ u64 add2(u64 a, u64 b) {
    u64 r; asm("add.rn.f32x2 %0, %1, %2;" : "=l"(r) : "l"(a), "l"(b)); return r;
}
__device__ __forceinline__ u64 mul2(u64 a, u64 b) {
    u64 r; asm("mul.rn.f32x2 %0, %1, %2;" : "=l"(r) : "l"(a), "l"(b)); return r;
}
__device__ __forceinline__ float ex2f(float x) {
    float r; asm("ex2.approx.f32 %0, %1;" : "=f"(r) : "f"(x)); return r;
}
__device__ __forceinline__ void cpasync16(void* smem_dst, const void* gsrc, int srcsz) {
    unsigned saddr = (unsigned)__cvta_generic_to_shared(smem_dst);
    asm volatile("cp.async.cg.shared.global [%0], [%1], 16, %2;"
                 :: "r"(saddr), "l"(gsrc), "r"(srcsz));
}
__device__ __forceinline__ void cpasync_commit() {
    asm volatile("cp.async.commit_group;");
}
__device__ __forceinline__ void cpasync_wait_all() {
    asm volatile("cp.async.wait_group 0;");
}

// ---------------- device scratch ----------------
__device__ float g_W[E_ * NCOLS];                    // repacked conv weights
__device__ float g_P[(size_t)NROWS * NCOLS];         // per-(row,type,tap) partials
__device__ float g_qn[3 * (size_t)QROWS * C_];       // normalized q n-gram feats
__device__ float g_dn[3 * (size_t)DROWS * C_];       // normalized d n-gram feats
__device__ float g_feats[B_ * 99];                   // pooled features [B, 9*11]

// ---------------- K0: repack conv weights into W[300][768] ----------------
__global__ void kw_build(const float* __restrict__ w1,
                         const float* __restrict__ w2,
                         const float* __restrict__ w3)
{
    int idx = blockIdx.x * 256 + threadIdx.x;
    if (idx >= E_ * NCOLS) return;
    int e = idx / NCOLS, col = idx % NCOLS;
    float v;
    if (col < 128) {
        v = w1[col * E_ + e];
    } else if (col < 384) {
        int u = col - 128; int t = u >> 7; int c = u & 127;
        v = w2[c * (E_ * 2) + e * 2 + t];
    } else {
        int u = col - 384; int t = u >> 7; int c = u & 127;
        v = w3[c * (E_ * 3) + e * 3 + t];
    }
    g_W[idx] = v;
}

// ---------------- K1: gather-GEMM P = Emb[tok] @ W  (f32x2, double-buffered) --------
// M=29440, K=300, N=768. Block tile 128x128, thread tile 8x8, KC=16, 19 k-tiles.
#define KTILES 19
__global__ __launch_bounds__(256, 2) void k1_gemm(const float* __restrict__ emb,
                                                  const int* __restrict__ qtok,
                                                  const int* __restrict__ dtok)
{
    __shared__ __align__(16) float As[2][16][128];   // [k][m]
    __shared__ __align__(16) float Bs[2][16][128];   // [k][n]
    const int tid = threadIdx.x;
    const int bm0 = blockIdx.x * 128;
    const int bn0 = blockIdx.y * 128;
    const int m0 = (tid & 15) * 8;
    const int n0 = (tid >> 4) * 8;

    // A loader: thread covers row am, k-slab of 8 at offset ah within the k-tile
    const int am = tid & 127;
    const int ah = (tid >> 7) * 8;
    const int r = bm0 + am;
    const int tok = (r < QROWS) ? qtok[r] : dtok[r - QROWS];
    const float* arow = emb + (size_t)tok * E_;
    // B loader: row bk, 8 cols at bc
    const int bk = tid >> 4;
    const int bc = (tid & 15) * 8;
    const float* brow = g_W + bn0 + bc;

    u64 acc[4][8];   // [m-pair][n]
#pragma unroll
    for (int i = 0; i < 4; i++)
#pragma unroll
        for (int j = 0; j < 8; j++) acc[i][j] = 0ull;

    float4 av0, av1;
    const float4 fz = make_float4(0.f, 0.f, 0.f, 0.f);

    // ---- prologue: tile 0 ----
    {
        int ka = ah;                 // t=0
        av0 = *(const float4*)(arow + ka);
        av1 = *(const float4*)(arow + ka + 4);
        int kb = bk;
        cpasync16(&Bs[0][bk][bc],     brow + (size_t)kb * NCOLS,     16);
        cpasync16(&Bs[0][bk][bc + 4], brow + (size_t)kb * NCOLS + 4, 16);
        cpasync_commit();
        As[0][ah + 0][am] = av0.x; As[0][ah + 1][am] = av0.y;
        As[0][ah + 2][am] = av0.z; As[0][ah + 3][am] = av0.w;
        As[0][ah + 4][am] = av1.x; As[0][ah + 5][am] = av1.y;
        As[0][ah + 6][am] = av1.z; As[0][ah + 7][am] = av1.w;
        cpasync_wait_all();
        __syncthreads();
    }

    int buf = 0;
    for (int t = 0; t < KTILES; t++) {
        // prefetch t+1
        if (t + 1 < KTILES) {
            int ka = (t + 1) * 16 + ah;
            av0 = *(const float4*)(arow + ka);                       // ka <= 296, in-bounds
            av1 = (ka + 4 < E_) ? *(const float4*)(arow + ka + 4) : fz;
            int kb = (t + 1) * 16 + bk;
            int sz = (kb < E_) ? 16 : 0;
            const float* bsrc = brow + (size_t)min(kb, E_ - 1) * NCOLS;
            cpasync16(&Bs[buf ^ 1][bk][bc],     bsrc,     sz);
            cpasync16(&Bs[buf ^ 1][bk][bc + 4], bsrc + 4, sz);
            cpasync_commit();
        }
        // compute current tile
#pragma unroll
        for (int kk = 0; kk < 16; kk++) {
            longlong2 la0 = *(const longlong2*)&As[buf][kk][m0];
            longlong2 la1 = *(const longlong2*)&As[buf][kk][m0 + 4];
            float4 b0 = *(const float4*)&Bs[buf][kk][n0];
            float4 b1 = *(const float4*)&Bs[buf][kk][n0 + 4];
            u64 ap[4] = { (u64)la0.x, (u64)la0.y, (u64)la1.x, (u64)la1.y };
            u64 bd[8] = { dupf(b0.x), dupf(b0.y), dupf(b0.z), dupf(b0.w),
                          dupf(b1.x), dupf(b1.y), dupf(b1.z), dupf(b1.w) };
#pragma unroll
            for (int i = 0; i < 4; i++)
#pragma unroll
                for (int j = 0; j < 8; j++)
                    ffma2(acc[i][j], ap[i], bd[j]);
        }
        if (t + 1 < KTILES) {
            int ka = (t + 1) * 16;
            (void)ka;
            As[buf ^ 1][ah + 0][am] = av0.x; As[buf ^ 1][ah + 1][am] = av0.y;
            As[buf ^ 1][ah + 2][am] = av0.z; As[buf ^ 1][ah + 3][am] = av0.w;
            As[buf ^ 1][ah + 4][am] = av1.x; As[buf ^ 1][ah + 5][am] = av1.y;
            As[buf ^ 1][ah + 6][am] = av1.z; As[buf ^ 1][ah + 7][am] = av1.w;
            cpasync_wait_all();
            __syncthreads();
        }
        buf ^= 1;
    }

    // store 8x8 tile
#pragma unroll
    for (int ip = 0; ip < 4; ip++) {
        float r0[8], r1[8];
#pragma unroll
        for (int j = 0; j < 8; j++) unpackf(acc[ip][j], r0[j], r1[j]);
        size_t row0 = (size_t)(bm0 + m0 + 2 * ip) * NCOLS + bn0 + n0;
        size_t row1 = row0 + NCOLS;
        *(float4*)&g_P[row0]     = make_float4(r0[0], r0[1], r0[2], r0[3]);
        *(float4*)&g_P[row0 + 4] = make_float4(r0[4], r0[5], r0[6], r0[7]);
        *(float4*)&g_P[row1]     = make_float4(r1[0], r1[1], r1[2], r1[3]);
        *(float4*)&g_P[row1 + 4] = make_float4(r1[4], r1[5], r1[6], r1[7]);
    }
}

// ---------------- K2: tap-combine + bias + ReLU + L2-normalize ----------------
__global__ void k2_combine(const float* __restrict__ cb1,
                           const float* __restrict__ cb2,
                           const float* __restrict__ cb3)
{
    const int r = blockIdx.x;
    const int c = threadIdx.x;
    int l, L, rr;
    const bool isq = (r < QROWS);
    if (isq) { rr = r;          l = r % Q_;  L = Q_; }
    else     { rr = r - QROWS;  l = rr % D_; L = D_; }

    const float* Pr = g_P + (size_t)r * NCOLS;
    float v1 = cb1[c] + Pr[c];
    float v2 = cb2[c] + Pr[128 + c];
    float v3 = cb3[c] + Pr[384 + c];
    if (l + 1 < L) { v2 += Pr[NCOLS + 256 + c]; v3 += Pr[NCOLS + 512 + c]; }
    if (l + 2 < L) { v3 += Pr[2 * NCOLS + 640 + c]; }
    v1 = fmaxf(v1, 0.f); v2 = fmaxf(v2, 0.f); v3 = fmaxf(v3, 0.f);

    float s1 = v1 * v1, s2 = v2 * v2, s3 = v3 * v3;
#pragma unroll
    for (int o = 16; o; o >>= 1) {
        s1 += __shfl_xor_sync(0xffffffffu, s1, o);
        s2 += __shfl_xor_sync(0xffffffffu, s2, o);
        s3 += __shfl_xor_sync(0xffffffffu, s3, o);
    }
    __shared__ float sred[3][4];
    const int lane = c & 31, w = c >> 5;
    if (lane == 0) { sred[0][w] = s1; sred[1][w] = s2; sred[2][w] = s3; }
    __syncthreads();
    float ss1 = sred[0][0] + sred[0][1] + sred[0][2] + sred[0][3];
    float ss2 = sred[1][0] + sred[1][1] + sred[1][2] + sred[1][3];
    float ss3 = sred[2][0] + sred[2][1] + sred[2][2] + sred[2][3];
    float n1 = v1 * (1.0f / (sqrtf(ss1) + 1e-13f));
    float n2 = v2 * (1.0f / (sqrtf(ss2) + 1e-13f));
    float n3 = v3 * (1.0f / (sqrtf(ss3) + 1e-13f));

    if (isq) {
        g_qn[((size_t)0 * QROWS + rr) * C_ + c] = n1;
        g_qn[((size_t)1 * QROWS + rr) * C_ + c] = n2;
        g_qn[((size_t)2 * QROWS + rr) * C_ + c] = n3;
    } else {
        g_dn[((size_t)0 * DROWS + rr) * C_ + c] = n1;
        g_dn[((size_t)1 * DROWS + rr) * C_ + c] = n2;
        g_dn[((size_t)2 * DROWS + rr) * C_ + c] = n3;
    }
}

// ---------------- K3: fused cosine GEMM + RBF soft-binning + log pooling ----------------
__global__ __launch_bounds__(128) void k3_pool(const int* __restrict__ qtok,
                                               const int* __restrict__ dtok)
{
    // -1/(2*sigma^2) * log2(e): wide kernels sigma=0.1 -> -50*log2e ; exact kernel sigma=.001
    const float AW = -72.134754f;          // -50 * log2(e)
    const float A0 = -7.2134754e8f;        // -5e5 * log2(e)

    __shared__ __align__(16) float qsT[128][36];   // [c][q], padded
    __shared__ __align__(16) float dsT[128][36];   // [c][d-chunk of 32]
    __shared__ float spk[32][11];
    __shared__ float qm[32];
    __shared__ float dm[224];

    const int b = blockIdx.x, pair = blockIdx.y;
    const int qi = pair / 3, dj = pair % 3;
    const int tid = threadIdx.x;

    if (tid < 32) qm[tid] = (tid < Q_ && qtok[b * Q_ + tid] > 0) ? 1.f : 0.f;
    for (int i = tid; i < 224; i += 128)
        dm[i] = (i < D_ && dtok[b * D_ + i] > 0) ? 1.f : 0.f;
    for (int i = tid; i < 32 * 11; i += 128) (&spk[0][0])[i] = 0.f;

    const float* qbase = g_qn + ((size_t)qi * QROWS + b * Q_) * C_;
    for (int i = 0; i < Q_; i++)
        qsT[tid][i] = qbase[(size_t)i * C_ + tid];
    qsT[tid][30] = 0.f; qsT[tid][31] = 0.f;

    const float* dbase = g_dn + ((size_t)dj * DROWS + b * D_) * C_;

    const int ty = tid >> 3, tx = tid & 7;
    const int q0 = ty * 2, d0 = tx * 4;

    // negated mus for wide kernels, packed in pairs (k1..k10)
    const u64 negmu2_0 = packf(-0.9f, -0.7f);
    const u64 negmu2_1 = packf(-0.5f, -0.3f);
    const u64 negmu2_2 = packf(-0.1f,  0.1f);
    const u64 negmu2_3 = packf( 0.3f,  0.5f);
    const u64 negmu2_4 = packf( 0.7f,  0.9f);
    const u64 aw2 = dupf(AW);

    u64 pkP[2][5];
    float pk0[2] = {0.f, 0.f};
#pragma unroll
    for (int i = 0; i < 2; i++)
#pragma unroll
        for (int p = 0; p < 5; p++) pkP[i][p] = 0ull;

    __syncthreads();

    for (int ch = 0; ch < 7; ch++) {
        const int dst = ch * 32;
#pragma unroll 4
        for (int i = 0; i < 32; i++) {
            int d = dst + i;
            dsT[tid][i] = (d < D_) ? dbase[(size_t)d * C_ + tid] : 0.f;
        }
        __syncthreads();

        // cosine GEMM 2x4 in f32x2 (pack along d)
        u64 csP[2][2];
        csP[0][0] = csP[0][1] = csP[1][0] = csP[1][1] = 0ull;
#pragma unroll 8
        for (int k = 0; k < 128; k++) {
            float2 a = *(const float2*)&qsT[k][q0];
            longlong2 lb = *(const longlong2*)&dsT[k][d0];
            u64 ax = dupf(a.x), ay = dupf(a.y);
            ffma2(csP[0][0], ax, (u64)lb.x); ffma2(csP[0][1], ax, (u64)lb.y);
            ffma2(csP[1][0], ay, (u64)lb.x); ffma2(csP[1][1], ay, (u64)lb.y);
        }

#pragma unroll
        for (int i = 0; i < 2; i++) {
            float cs[4];
            unpackf(csP[i][0], cs[0], cs[1]);
            unpackf(csP[i][1], cs[2], cs[3]);
            float qmi = qm[q0 + i];
#pragma unroll
            for (int j = 0; j < 4; j++) {
                float m  = qmi * dm[dst + d0 + j];
                float c  = cs[j] * m;               // masked cosine
                // exact-match kernel (mu=1, sigma=1e-3)
                float df0 = c - 1.0f;
                pk0[i] = fmaf(m, ex2f(df0 * df0 * A0), pk0[i]);
                // 10 wide kernels, 5 packed pairs
                u64 c2 = dupf(c), m2 = dupf(m);
#pragma unroll
                for (int p = 0; p < 5; p++) {
                    u64 nmu = (p == 0) ? negmu2_0 : (p == 1) ? negmu2_1 :
                              (p == 2) ? negmu2_2 : (p == 3) ? negmu2_3 : negmu2_4;
                    u64 df = add2(c2, nmu);
                    u64 s  = mul2(df, df);
                    u64 ar = mul2(s, aw2);
                    float lo, hi; unpackf(ar, lo, hi);
                    u64 e2 = packf(ex2f(lo), ex2f(hi));
                    ffma2(pkP[i][p], m2, e2);
                }
            }
        }
        __syncthreads();
    }

#pragma unroll
    for (int i = 0; i < 2; i++) {
        atomicAdd(&spk[q0 + i][0], pk0[i]);
#pragma unroll
        for (int p = 0; p < 5; p++) {
            float lo, hi; unpackf(pkP[i][p], lo, hi);
            atomicAdd(&spk[q0 + i][1 + 2 * p], lo);
            atomicAdd(&spk[q0 + i][2 + 2 * p], hi);
        }
    }
    __syncthreads();

    if (tid < 11) {
        float f = 0.f;
        for (int q = 0; q < Q_; q++)
            f += logf(fmaxf(spk[q][tid], 1e-10f)) * 0.01f * qm[q];
        g_feats[(b * 9 + pair) * 11 + tid] = f;
    }
}

// ---------------- K4: final dense [B,99] @ w[99] ----------------
__global__ void k4_out(const float* __restrict__ dw, float* __restrict__ out)
{
    int b = threadIdx.x;
    float f = 0.f;
#pragma unroll
    for (int j = 0; j < 99; j++) f += g_feats[b * 99 + j] * dw[j];
    out[b] = f;
}

// ---------------- launch ----------------
extern "C" void kernel_launch(void* const* d_in, const int* in_sizes, int n_in,
                              void* d_out, int out_size)
{
    (void)in_sizes; (void)n_in; (void)out_size;
    const int*   qtok = (const int*)d_in[0];
    const int*   dtok = (const int*)d_in[1];
    const float* emb  = (const float*)d_in[2];
    const float* w1   = (const float*)d_in[3];
    const float* w2   = (const float*)d_in[4];
    const float* w3   = (const float*)d_in[5];
    const float* cb1  = (const float*)d_in[6];
    const float* cb2  = (const float*)d_in[7];
    const float* cb3  = (const float*)d_in[8];
    const float* dw   = (const float*)d_in[9];
    float* out = (float*)d_out;

    kw_build<<<(E_ * NCOLS + 255) / 256, 256>>>(w1, w2, w3);
    k1_gemm<<<dim3(230, 6), 256>>>(emb, qtok, dtok);
    k2_combine<<<NROWS, 128>>>(cb1, cb2, cb3);
    k3_pool<<<dim3(128, 9), 128>>>(qtok, dtok);
    k4_out<<<1, 128>>>(dw, out);
}

// round 4
// speedup vs baseline: 2.1524x; 1.4533x over previous
#include <cuda_runtime.h>
#include <cuda_bf16.h>
#include <cstdint>

// Problem constants
#define B_    128
#define Q_    30
#define D_    200
#define E_    300
#define C_    128
#define QROWS 3840
#define DROWS 25600
#define NROWS 29440          // 230 * 128
#define NCOLS 768
#define KP    320            // padded K per split-pass

typedef unsigned long long u64;

// ================= f32x2 helpers (k3) =================
__device__ __forceinline__ u64 dupf(float x) {
    u64 r; unsigned xi = __float_as_uint(x);
    asm("mov.b64 %0, {%1, %1};" : "=l"(r) : "r"(xi));
    return r;
}
__device__ __forceinline__ u64 packf(float lo, float hi) {
    u64 r; unsigned a = __float_as_uint(lo), b = __float_as_uint(hi);
    asm("mov.b64 %0, {%1, %2};" : "=l"(r) : "r"(a), "r"(b));
    return r;
}
__device__ __forceinline__ void unpackf(u64 v, float& lo, float& hi) {
    unsigned a, b;
    asm("mov.b64 {%0, %1}, %2;" : "=r"(a), "=r"(b) : "l"(v));
    lo = __uint_as_float(a); hi = __uint_as_float(b);
}
__device__ __forceinline__ void ffma2(u64& d, u64 a, u64 b) {
    asm("fma.rn.f32x2 %0, %1, %2, %0;" : "+l"(d) : "l"(a), "l"(b));
}
__device__ __forceinline__ u64 add2(u64 a, u64 b) {
    u64 r; asm("add.rn.f32x2 %0, %1, %2;" : "=l"(r) : "l"(a), "l"(b)); return r;
}
__device__ __forceinline__ u64 mul2(u64 a, u64 b) {
    u64 r; asm("mul.rn.f32x2 %0, %1, %2;" : "=l"(r) : "l"(a), "l"(b)); return r;
}
__device__ __forceinline__ float ex2f(float x) {
    float r; asm("ex2.approx.f32 %0, %1;" : "=f"(r) : "f"(x)); return r;
}
__device__ __forceinline__ void cpasync16(uint32_t sdst, const void* gsrc) {
    asm volatile("cp.async.cg.shared.global [%0], [%1], 16;" :: "r"(sdst), "l"(gsrc));
}
__device__ __forceinline__ uint32_t smem_u32(const void* p) {
    uint32_t a;
    asm("{ .reg .u64 t; cvta.to.shared.u64 t, %1; cvt.u32.u64 %0, t; }" : "=r"(a) : "l"(p));
    return a;
}
__device__ __forceinline__ void ldmatrix_x4(uint32_t* r, uint32_t saddr) {
    asm volatile("ldmatrix.sync.aligned.m8n8.x4.shared.b16 {%0,%1,%2,%3}, [%4];"
                 : "=r"(r[0]), "=r"(r[1]), "=r"(r[2]), "=r"(r[3]) : "r"(saddr));
}
__device__ __forceinline__ void mma_bf16(float* c, const uint32_t* a,
                                         uint32_t b0, uint32_t b1) {
    asm volatile("mma.sync.aligned.m16n8k16.row.col.f32.bf16.bf16.f32 "
                 "{%0,%1,%2,%3}, {%4,%5,%6,%7}, {%8,%9}, {%0,%1,%2,%3};"
                 : "+f"(c[0]), "+f"(c[1]), "+f"(c[2]), "+f"(c[3])
                 : "r"(a[0]), "r"(a[1]), "r"(a[2]), "r"(a[3]), "r"(b0), "r"(b1));
}

// ================= device scratch =================
__device__ __nv_bfloat16 g_Ahi[(size_t)NROWS * KP];
__device__ __nv_bfloat16 g_Alo[(size_t)NROWS * KP];
__device__ __nv_bfloat16 g_Whi[(size_t)NCOLS * KP];
__device__ __nv_bfloat16 g_Wlo[(size_t)NCOLS * KP];
__device__ float g_P[(size_t)NROWS * NCOLS];
__device__ float g_qn[3 * (size_t)QROWS * C_];
__device__ float g_dn[3 * (size_t)DROWS * C_];
__device__ float g_feats[B_ * 99];

// ================= pack kernels =================
__global__ void pack_W(const float* __restrict__ w1,
                       const float* __restrict__ w2,
                       const float* __restrict__ w3)
{
    int idx = blockIdx.x * 256 + threadIdx.x;
    if (idx >= NCOLS * KP) return;
    int n = idx / KP, k = idx % KP;
    float v = 0.f;
    if (k < E_) {
        if (n < 128)       v = w1[n * E_ + k];
        else if (n < 384) { int u = n - 128; v = w2[(u & 127) * (E_ * 2) + k * 2 + (u >> 7)]; }
        else              { int u = n - 384; v = w3[(u & 127) * (E_ * 3) + k * 3 + (u >> 7)]; }
    }
    __nv_bfloat16 h = __float2bfloat16(v);
    __nv_bfloat16 l = __float2bfloat16(v - __bfloat162float(h));
    g_Whi[idx] = h; g_Wlo[idx] = l;
}

__global__ void pack_A(const float* __restrict__ emb,
                       const int* __restrict__ qtok,
                       const int* __restrict__ dtok)
{
    int idx = blockIdx.x * 256 + threadIdx.x;
    if (idx >= NROWS * (KP / 4)) return;
    int r = idx / (KP / 4), g = idx % (KP / 4);
    int k = g * 4;
    float4 v = make_float4(0.f, 0.f, 0.f, 0.f);
    if (k < E_) {
        int tok = (r < QROWS) ? qtok[r] : dtok[r - QROWS];
        v = *(const float4*)(emb + (size_t)tok * E_ + k);
    }
    float vv[4] = {v.x, v.y, v.z, v.w};
    u64 hw = 0, lw = 0;
#pragma unroll
    for (int i = 0; i < 4; i++) {
        __nv_bfloat16 h = __float2bfloat16(vv[i]);
        __nv_bfloat16 l = __float2bfloat16(vv[i] - __bfloat162float(h));
        hw |= (u64)(*(unsigned short*)&h) << (16 * i);
        lw |= (u64)(*(unsigned short*)&l) << (16 * i);
    }
    *(u64*)(g_Ahi + (size_t)r * KP + k) = hw;
    *(u64*)(g_Alo + (size_t)r * KP + k) = lw;
}

// ================= K1: HMMA GEMM  P = A' @ W'^T  (bf16 split, K'=960) =================
// CTA tile 128x256, 8 warps (2x4), warp tile 64x64, KC=32, 3-stage cp.async pipeline.
#define KC        32
#define NCHUNK    30
#define A_BYTES   (128 * 64)       // 128 rows * 64B (32 bf16)
#define B_BYTES   (256 * 64)
#define STAGE_B   (A_BYTES + B_BYTES)
#define K1_SMEM   (3 * STAGE_B)    // 73728

// swizzled byte offset of 16B chunk `ch` (0..3) in row `row` (64B rows)
__device__ __forceinline__ uint32_t swz(int row, int ch) {
    return (uint32_t)(row * 64 + ((ch ^ ((row >> 1) & 3)) << 4));
}

__global__ __launch_bounds__(256, 1) void k1h()
{
    extern __shared__ char smem[];
    const uint32_t sb = smem_u32(smem);
    const int tid = threadIdx.x;
    const int lane = tid & 31;
    const int wid = tid >> 5;
    const int warp_m = wid & 1;        // 0..1
    const int warp_n = wid >> 1;       // 0..3
    const int bm0 = blockIdx.x * 128;
    const int bn0 = blockIdx.y * 256;

    float c[4][8][4];
#pragma unroll
    for (int i = 0; i < 4; i++)
#pragma unroll
        for (int j = 0; j < 8; j++)
#pragma unroll
            for (int k = 0; k < 4; k++) c[i][j][k] = 0.f;

    auto load_stage = [&](int chunk, int st) {
        const int pass = chunk / 10;
        const int kloc = (chunk % 10) * KC;
        const __nv_bfloat16* As = (pass == 2) ? g_Alo : g_Ahi;
        const __nv_bfloat16* Bs = (pass == 1) ? g_Wlo : g_Whi;
        const uint32_t aB = sb + st * STAGE_B;
        const uint32_t bB = aB + A_BYTES;
#pragma unroll
        for (int j = 0; j < 2; j++) {
            int u = tid + j * 256;             // 0..511 : A 128 rows x 4 chunks
            int row = u >> 2, ch = u & 3;
            cpasync16(aB + swz(row, ch), As + (size_t)(bm0 + row) * KP + kloc + ch * 8);
        }
#pragma unroll
        for (int j = 0; j < 4; j++) {
            int u = tid + j * 256;             // 0..1023 : B 256 rows x 4 chunks
            int row = u >> 2, ch = u & 3;
            cpasync16(bB + swz(row, ch), Bs + (size_t)(bn0 + row) * KP + kloc + ch * 8);
        }
        asm volatile("cp.async.commit_group;");
    };

    load_stage(0, 0);
    load_stage(1, 1);

    const int rit = (lane & 7) + ((lane >> 3) & 1) * 8;   // ldmatrix row-in-tile

    for (int cidx = 0; cidx < NCHUNK; cidx++) {
        const int st = cidx % 3;
        if (cidx < NCHUNK - 1) asm volatile("cp.async.wait_group 1;");
        else                   asm volatile("cp.async.wait_group 0;");
        __syncthreads();
        if (cidx + 2 < NCHUNK) load_stage(cidx + 2, (cidx + 2) % 3);

        const uint32_t aB = sb + st * STAGE_B;
        const uint32_t bB = aB + A_BYTES;
#pragma unroll
        for (int ks = 0; ks < 2; ks++) {
            const int kch = ks * 2 + (lane >> 4);
            uint32_t a[4][4], b[4][4];
#pragma unroll
            for (int mi = 0; mi < 4; mi++) {
                int r = warp_m * 64 + mi * 16 + rit;
                ldmatrix_x4(a[mi], aB + swz(r, kch));
            }
#pragma unroll
            for (int nj = 0; nj < 4; nj++) {
                int r = warp_n * 64 + nj * 16 + rit;
                ldmatrix_x4(b[nj], bB + swz(r, kch));
            }
#pragma unroll
            for (int mi = 0; mi < 4; mi++)
#pragma unroll
                for (int nj = 0; nj < 4; nj++) {
                    mma_bf16(c[mi][2 * nj],     a[mi], b[nj][0], b[nj][2]);
                    mma_bf16(c[mi][2 * nj + 1], a[mi], b[nj][1], b[nj][3]);
                }
        }
        __syncthreads();
    }

    // epilogue: store 64x64 warp tile
#pragma unroll
    for (int mi = 0; mi < 4; mi++) {
        const int r0 = bm0 + warp_m * 64 + mi * 16 + (lane >> 2);
#pragma unroll
        for (int nj = 0; nj < 4; nj++) {
#pragma unroll
            for (int h = 0; h < 2; h++) {
                const float* cc = c[mi][2 * nj + h];
                const int col = bn0 + warp_n * 64 + nj * 16 + h * 8 + (lane & 3) * 2;
                *(float2*)&g_P[(size_t)r0 * NCOLS + col]       = make_float2(cc[0], cc[1]);
                *(float2*)&g_P[(size_t)(r0 + 8) * NCOLS + col] = make_float2(cc[2], cc[3]);
            }
        }
    }
}

// ================= K2: tap-combine + bias + ReLU + L2-normalize =================
__global__ void k2_combine(const float* __restrict__ cb1,
                           const float* __restrict__ cb2,
                           const float* __restrict__ cb3)
{
    const int r = blockIdx.x;
    const int c = threadIdx.x;
    int l, L, rr;
    const bool isq = (r < QROWS);
    if (isq) { rr = r;          l = r % Q_;  L = Q_; }
    else     { rr = r - QROWS;  l = rr % D_; L = D_; }

    const float* Pr = g_P + (size_t)r * NCOLS;
    float v1 = cb1[c] + Pr[c];
    float v2 = cb2[c] + Pr[128 + c];
    float v3 = cb3[c] + Pr[384 + c];
    if (l + 1 < L) { v2 += Pr[NCOLS + 256 + c]; v3 += Pr[NCOLS + 512 + c]; }
    if (l + 2 < L) { v3 += Pr[2 * NCOLS + 640 + c]; }
    v1 = fmaxf(v1, 0.f); v2 = fmaxf(v2, 0.f); v3 = fmaxf(v3, 0.f);

    float s1 = v1 * v1, s2 = v2 * v2, s3 = v3 * v3;
#pragma unroll
    for (int o = 16; o; o >>= 1) {
        s1 += __shfl_xor_sync(0xffffffffu, s1, o);
        s2 += __shfl_xor_sync(0xffffffffu, s2, o);
        s3 += __shfl_xor_sync(0xffffffffu, s3, o);
    }
    __shared__ float sred[3][4];
    const int lane = c & 31, w = c >> 5;
    if (lane == 0) { sred[0][w] = s1; sred[1][w] = s2; sred[2][w] = s3; }
    __syncthreads();
    float ss1 = sred[0][0] + sred[0][1] + sred[0][2] + sred[0][3];
    float ss2 = sred[1][0] + sred[1][1] + sred[1][2] + sred[1][3];
    float ss3 = sred[2][0] + sred[2][1] + sred[2][2] + sred[2][3];
    float n1 = v1 * (1.0f / (sqrtf(ss1) + 1e-13f));
    float n2 = v2 * (1.0f / (sqrtf(ss2) + 1e-13f));
    float n3 = v3 * (1.0f / (sqrtf(ss3) + 1e-13f));

    if (isq) {
        g_qn[((size_t)0 * QROWS + rr) * C_ + c] = n1;
        g_qn[((size_t)1 * QROWS + rr) * C_ + c] = n2;
        g_qn[((size_t)2 * QROWS + rr) * C_ + c] = n3;
    } else {
        g_dn[((size_t)0 * DROWS + rr) * C_ + c] = n1;
        g_dn[((size_t)1 * DROWS + rr) * C_ + c] = n2;
        g_dn[((size_t)2 * DROWS + rr) * C_ + c] = n3;
    }
}

// ================= K3: fused cosine GEMM + RBF + log pooling =================
__global__ __launch_bounds__(128) void k3_pool(const int* __restrict__ qtok,
                                               const int* __restrict__ dtok)
{
    const float AW = -72.134754f;          // -50 * log2(e)
    const float A0 = -7.2134754e8f;        // -5e5 * log2(e)

    __shared__ __align__(16) float qsT[128][36];
    __shared__ __align__(16) float dsT[128][36];
    __shared__ float spk[32][11];
    __shared__ float qm[32];
    __shared__ float dm[224];

    const int b = blockIdx.x, pair = blockIdx.y;
    const int qi = pair / 3, dj = pair % 3;
    const int tid = threadIdx.x;

    if (tid < 32) qm[tid] = (tid < Q_ && qtok[b * Q_ + tid] > 0) ? 1.f : 0.f;
    for (int i = tid; i < 224; i += 128)
        dm[i] = (i < D_ && dtok[b * D_ + i] > 0) ? 1.f : 0.f;
    for (int i = tid; i < 32 * 11; i += 128) (&spk[0][0])[i] = 0.f;

    const float* qbase = g_qn + ((size_t)qi * QROWS + b * Q_) * C_;
    for (int i = 0; i < Q_; i++)
        qsT[tid][i] = qbase[(size_t)i * C_ + tid];
    qsT[tid][30] = 0.f; qsT[tid][31] = 0.f;

    const float* dbase = g_dn + ((size_t)dj * DROWS + b * D_) * C_;

    const int ty = tid >> 3, tx = tid & 7;
    const int q0 = ty * 2, d0 = tx * 4;

    const u64 negmu2_0 = packf(-0.9f, -0.7f);
    const u64 negmu2_1 = packf(-0.5f, -0.3f);
    const u64 negmu2_2 = packf(-0.1f,  0.1f);
    const u64 negmu2_3 = packf( 0.3f,  0.5f);
    const u64 negmu2_4 = packf( 0.7f,  0.9f);
    const u64 aw2 = dupf(AW);

    u64 pkP[2][5];
    float pk0[2] = {0.f, 0.f};
#pragma unroll
    for (int i = 0; i < 2; i++)
#pragma unroll
        for (int p = 0; p < 5; p++) pkP[i][p] = 0ull;

    __syncthreads();

    for (int ch = 0; ch < 7; ch++) {
        const int dst = ch * 32;
#pragma unroll 4
        for (int i = 0; i < 32; i++) {
            int d = dst + i;
            dsT[tid][i] = (d < D_) ? dbase[(size_t)d * C_ + tid] : 0.f;
        }
        __syncthreads();

        u64 csP[2][2];
        csP[0][0] = csP[0][1] = csP[1][0] = csP[1][1] = 0ull;
#pragma unroll 8
        for (int k = 0; k < 128; k++) {
            float2 a = *(const float2*)&qsT[k][q0];
            longlong2 lb = *(const longlong2*)&dsT[k][d0];
            u64 ax = dupf(a.x), ay = dupf(a.y);
            ffma2(csP[0][0], ax, (u64)lb.x); ffma2(csP[0][1], ax, (u64)lb.y);
            ffma2(csP[1][0], ay, (u64)lb.x); ffma2(csP[1][1], ay, (u64)lb.y);
        }

#pragma unroll
        for (int i = 0; i < 2; i++) {
            float cs[4];
            unpackf(csP[i][0], cs[0], cs[1]);
            unpackf(csP[i][1], cs[2], cs[3]);
            float qmi = qm[q0 + i];
#pragma unroll
            for (int j = 0; j < 4; j++) {
                float m  = qmi * dm[dst + d0 + j];
                float c  = cs[j] * m;
                float df0 = c - 1.0f;
                pk0[i] = fmaf(m, ex2f(df0 * df0 * A0), pk0[i]);
                u64 c2 = dupf(c), m2 = dupf(m);
#pragma unroll
                for (int p = 0; p < 5; p++) {
                    u64 nmu = (p == 0) ? negmu2_0 : (p == 1) ? negmu2_1 :
                              (p == 2) ? negmu2_2 : (p == 3) ? negmu2_3 : negmu2_4;
                    u64 df = add2(c2, nmu);
                    u64 s  = mul2(df, df);
                    u64 ar = mul2(s, aw2);
                    float lo, hi; unpackf(ar, lo, hi);
                    u64 e2 = packf(ex2f(lo), ex2f(hi));
                    ffma2(pkP[i][p], m2, e2);
                }
            }
        }
        __syncthreads();
    }

#pragma unroll
    for (int i = 0; i < 2; i++) {
        atomicAdd(&spk[q0 + i][0], pk0[i]);
#pragma unroll
        for (int p = 0; p < 5; p++) {
            float lo, hi; unpackf(pkP[i][p], lo, hi);
            atomicAdd(&spk[q0 + i][1 + 2 * p], lo);
            atomicAdd(&spk[q0 + i][2 + 2 * p], hi);
        }
    }
    __syncthreads();

    if (tid < 11) {
        float f = 0.f;
        for (int q = 0; q < Q_; q++)
            f += logf(fmaxf(spk[q][tid], 1e-10f)) * 0.01f * qm[q];
        g_feats[(b * 9 + pair) * 11 + tid] = f;
    }
}

// ================= K4: final dense =================
__global__ void k4_out(const float* __restrict__ dw, float* __restrict__ out)
{
    int b = threadIdx.x;
    float f = 0.f;
#pragma unroll
    for (int j = 0; j < 99; j++) f += g_feats[b * 99 + j] * dw[j];
    out[b] = f;
}

// ================= launch =================
extern "C" void kernel_launch(void* const* d_in, const int* in_sizes, int n_in,
                              void* d_out, int out_size)
{
    (void)in_sizes; (void)n_in; (void)out_size;
    const int*   qtok = (const int*)d_in[0];
    const int*   dtok = (const int*)d_in[1];
    const float* emb  = (const float*)d_in[2];
    const float* w1   = (const float*)d_in[3];
    const float* w2   = (const float*)d_in[4];
    const float* w3   = (const float*)d_in[5];
    const float* cb1  = (const float*)d_in[6];
    const float* cb2  = (const float*)d_in[7];
    const float* cb3  = (const float*)d_in[8];
    const float* dw   = (const float*)d_in[9];
    float* out = (float*)d_out;

    cudaFuncSetAttribute(k1h, cudaFuncAttributeMaxDynamicSharedMemorySize, K1_SMEM);

    pack_W<<<(NCOLS * KP + 255) / 256, 256>>>(w1, w2, w3);
    pack_A<<<(NROWS * (KP / 4) + 255) / 256, 256>>>(emb, qtok, dtok);
    k1h<<<dim3(230, 3), 256, K1_SMEM>>>();
    k2_combine<<<NROWS, 128>>>(cb1, cb2, cb3);
    k3_pool<<<dim3(128, 9), 128>>>(qtok, dtok);
    k4_out<<<1, 128>>>(dw, out);
}